// round 7
// baseline (speedup 1.0000x reference)
#include <cuda_runtime.h>
#include <cuda_bf16.h>
#include <math.h>
#include <stdint.h>

#define BB 64
#define TT 2048
#define DD 128
#define UU 128
#define WPAD 136                        // W row pad (bf16 elems) -> conflict-free frags
#define RPAD 132                        // raw x row pad (fp32 elems)
#define NTILE 16
#define NT (BB * NTILE)                 // 1024 tiles
#define GRID 148
#define TSTRIDE 132                     // 128 ctx + m + s + pad

__device__ float g_tile[NT * TSTRIDE];
__device__ unsigned int g_done;         // zero-init; reset by last CTA each run

// ---- smem layout (bytes) ----
#define S_BIAS 0                        // float[128]
#define S_V    512                      // float[128]
#define S_PART 1024                     // float[2][128]
#define S_SC   2048                     // float[128]
#define S_RED  2560                     // float[8]
#define S_FLAG 2624                     // int
#define S_CTX  2688                     // float[4][128]
#define S_CMB  4736                     // wgt[64][16] + invS[64]
#define S_RAW  9216                     // 2 x float[128][RPAD] = 2 x 67584
#define S_WHI  (S_RAW + 2 * 128 * RPAD * 4)       // 144384
#define S_WLO  (S_WHI + 128 * WPAD * 2)           // 179200
#define S_TOTAL (S_WLO + 128 * WPAD * 2)          // 214016 B

__device__ __forceinline__ uint32_t smem_u32(const void* p) {
    uint32_t a;
    asm("{ .reg .u64 t; cvta.to.shared.u64 t, %1; cvt.u32.u64 %0, t; }" : "=r"(a) : "l"(p));
    return a;
}
#define CP_ASYNC16(dst, src) \
    asm volatile("cp.async.cg.shared.global [%0], [%1], 16;" :: "r"(dst), "l"(src) : "memory")
#define CP_COMMIT() asm volatile("cp.async.commit_group;" ::: "memory")
#define CP_WAIT0()  asm volatile("cp.async.wait_group 0;" ::: "memory")

__device__ __forceinline__ void mma16816(float* c, const uint32_t* a, const uint32_t* b) {
    asm volatile(
        "mma.sync.aligned.m16n8k16.row.col.f32.bf16.bf16.f32 "
        "{%0,%1,%2,%3}, {%4,%5,%6,%7}, {%8,%9}, {%0,%1,%2,%3};"
        : "+f"(c[0]), "+f"(c[1]), "+f"(c[2]), "+f"(c[3])
        : "r"(a[0]), "r"(a[1]), "r"(a[2]), "r"(a[3]), "r"(b[0]), "r"(b[1]));
}
__device__ __forceinline__ float tanh_ap(float x) {
    float r;
    asm("tanh.approx.f32 %0, %1;" : "=f"(r) : "f"(x));
    return r;
}
// split a float2 into packed bf16x2 hi and lo
__device__ __forceinline__ void split2(float2 v, uint32_t& hi, uint32_t& lo) {
    __nv_bfloat162 h = __float22bfloat162_rn(v);
    float2 hf = __bfloat1622float2(h);
    __nv_bfloat162 l = __float22bfloat162_rn(make_float2(v.x - hf.x, v.y - hf.y));
    hi = *(uint32_t*)&h;
    lo = *(uint32_t*)&l;
}

__global__ void __launch_bounds__(256, 1) fused_kernel(const float* __restrict__ x,
                                                       const float* __restrict__ W1,
                                                       const float* __restrict__ W2,
                                                       const float* __restrict__ b1,
                                                       const float* __restrict__ b2,
                                                       const float* __restrict__ Vw,
                                                       float* __restrict__ out) {
    extern __shared__ __align__(16) char smem[];
    const int tid = threadIdx.x, wid = tid >> 5, lane = tid & 31;
    const int g = lane >> 2, q = lane & 3;
    const int wm = wid & 3, wn = wid >> 2;
    float* raw0 = (float*)(smem + S_RAW);

    // ---- one-time: bias/V; Wsum staged (plain layout) then transpose-split ----
    if (tid < 128) {
        ((float*)(smem + S_BIAS))[tid] = b1[tid] + b2[tid];
        ((float*)(smem + S_V))[tid] = Vw[tid];
    }
    {
        const float4* w1 = (const float4*)W1;
        const float4* w2 = (const float4*)W2;
        float4* r4 = (float4*)raw0;
#pragma unroll
        for (int i = tid; i < 4096; i += 256) {
            float4 a = w1[i], b = w2[i];
            float4 c;
            c.x = a.x + b.x; c.y = a.y + b.y; c.z = a.z + b.z; c.w = a.w + b.w;
            r4[i] = c;
        }
    }
    __syncthreads();
    {
        const int u = tid & 127;
        const int k0 = (tid >> 7) * 64;
#pragma unroll
        for (int k = k0; k < k0 + 64; k += 2) {
            float2 w = make_float2(raw0[k * 128 + u], raw0[(k + 1) * 128 + u]);
            uint32_t hi, lo;
            split2(w, hi, lo);
            *(uint32_t*)(smem + S_WHI + (u * WPAD + k) * 2) = hi;
            *(uint32_t*)(smem + S_WLO + (u * WPAD + k) * 2) = lo;
        }
    }
    __syncthreads();

    // ---- prologue: fetch first tile into buffer 0 ----
    const uint32_t raw_addr0 = smem_u32(smem + S_RAW);
    int tile = blockIdx.x;
    if (tile < NT) {
#pragma unroll
        for (int n = 0; n < 16; n++) {
            int id = tid + n * 256;
            int r = id >> 5, c = id & 31;
            CP_ASYNC16(raw_addr0 + (uint32_t)(r * RPAD * 4 + c * 16),
                       (const char*)(x + (size_t)tile * 16384 + r * 128 + c * 4));
        }
        CP_COMMIT();
    }

    int it = 0;
    for (; tile < NT; tile += GRID, it++) {
        const int buf = it & 1;
        const float* rawf = (const float*)(smem + S_RAW + buf * 128 * RPAD * 4);
        CP_WAIT0();
        __syncthreads();

        // prefetch next tile into other buffer (overlaps compute)
        {
            const int next = tile + GRID;
            if (next < NT) {
                const uint32_t dst = raw_addr0 + (uint32_t)((buf ^ 1) * 128 * RPAD * 4);
#pragma unroll
                for (int n = 0; n < 16; n++) {
                    int id = tid + n * 256;
                    int r = id >> 5, c = id & 31;
                    CP_ASYNC16(dst + (uint32_t)(r * RPAD * 4 + c * 16),
                               (const char*)(x + (size_t)next * 16384 + r * 128 + c * 4));
                }
                CP_COMMIT();
            }
        }

        // ---- mainloop: A converted in-register from raw fp32; 3-term split ----
        float acc[2][8][4];
#pragma unroll
        for (int t = 0; t < 2; t++)
#pragma unroll
            for (int j = 0; j < 8; j++)
#pragma unroll
                for (int e = 0; e < 4; e++) acc[t][j][e] = 0.f;

#pragma unroll
        for (int ks = 0; ks < 8; ks++) {
            const int k0 = ks * 16;
            uint32_t ah[2][4], al[2][4];
#pragma unroll
            for (int t = 0; t < 2; t++) {
                const int row = wm * 32 + t * 16 + g;
                float2 v0 = *(const float2*)&rawf[row * RPAD + k0 + 2 * q];
                float2 v1 = *(const float2*)&rawf[(row + 8) * RPAD + k0 + 2 * q];
                float2 v2 = *(const float2*)&rawf[row * RPAD + k0 + 8 + 2 * q];
                float2 v3 = *(const float2*)&rawf[(row + 8) * RPAD + k0 + 8 + 2 * q];
                split2(v0, ah[t][0], al[t][0]);
                split2(v1, ah[t][1], al[t][1]);
                split2(v2, ah[t][2], al[t][2]);
                split2(v3, ah[t][3], al[t][3]);
            }
#pragma unroll
            for (int j = 0; j < 8; j++) {
                const int boff = ((wn * 64 + j * 8 + g) * WPAD + k0 + 2 * q) * 2;
                uint32_t bh[2], bl[2];
                bh[0] = *(const uint32_t*)(smem + S_WHI + boff);
                bh[1] = *(const uint32_t*)(smem + S_WHI + boff + 16);
                bl[0] = *(const uint32_t*)(smem + S_WLO + boff);
                bl[1] = *(const uint32_t*)(smem + S_WLO + boff + 16);
                mma16816(acc[0][j], ah[0], bh);
                mma16816(acc[1][j], ah[1], bh);
                mma16816(acc[0][j], ah[0], bl);
                mma16816(acc[1][j], ah[1], bl);
                mma16816(acc[0][j], al[0], bh);
                mma16816(acc[1][j], al[1], bh);
            }
        }

        // ---- epilogue: tanh (MUFU.TANH) + V-dot ----
        const float* sBias = (const float*)(smem + S_BIAS);
        const float* sV = (const float*)(smem + S_V);
        float p[4] = {0.f, 0.f, 0.f, 0.f};
#pragma unroll
        for (int t = 0; t < 2; t++) {
#pragma unroll
            for (int j = 0; j < 8; j++) {
                const int u0 = wn * 64 + j * 8 + 2 * q;
                const float bia0 = sBias[u0], bia1 = sBias[u0 + 1];
                const float v0 = sV[u0], v1 = sV[u0 + 1];
                p[t * 2 + 0] += tanh_ap(acc[t][j][0] + bia0) * v0
                              + tanh_ap(acc[t][j][1] + bia1) * v1;
                p[t * 2 + 1] += tanh_ap(acc[t][j][2] + bia0) * v0
                              + tanh_ap(acc[t][j][3] + bia1) * v1;
            }
        }
#pragma unroll
        for (int e = 0; e < 4; e++) {
            p[e] += __shfl_xor_sync(~0u, p[e], 1);
            p[e] += __shfl_xor_sync(~0u, p[e], 2);
        }
        if (q == 0) {
            float* part = (float*)(smem + S_PART);
            part[wn * 128 + wm * 32 + g]      = p[0];
            part[wn * 128 + wm * 32 + g + 8]  = p[1];
            part[wn * 128 + wm * 32 + g + 16] = p[2];
            part[wn * 128 + wm * 32 + g + 24] = p[3];
        }
        __syncthreads();
        float* sc = (float*)(smem + S_SC);
        if (tid < 128) {
            const float* part = (const float*)(smem + S_PART);
            sc[tid] = part[tid] + part[128 + tid];
        }
        __syncthreads();

        // ---- tile softmax stats ----
        float* red = (float*)(smem + S_RED);
        {
            float v = sc[tid & 127];
#pragma unroll
            for (int off = 16; off > 0; off >>= 1) v = fmaxf(v, __shfl_xor_sync(~0u, v, off));
            if (lane == 0) red[wid] = v;
        }
        __syncthreads();
        float M = fmaxf(fmaxf(red[0], red[1]), fmaxf(red[2], red[3]));
        M = fmaxf(M, fmaxf(fmaxf(red[4], red[5]), fmaxf(red[6], red[7])));
        __syncthreads();
        float e_val = 0.f;
        if (tid < 128) e_val = __expf(sc[tid] - M);
        {
            float v = e_val;
#pragma unroll
            for (int off = 16; off > 0; off >>= 1) v += __shfl_xor_sync(~0u, v, off);
            if (lane == 0) red[wid] = v;
        }
        if (tid < 128) sc[tid] = e_val;
        __syncthreads();
        const float S = red[0] + red[1] + red[2] + red[3];

        // ---- tile context from raw fp32 ----
        {
            const int h = tid >> 6;
            const int pp = tid & 63;
            float2 cacc = make_float2(0.f, 0.f);
#pragma unroll 8
            for (int i = 0; i < 32; i++) {
                const int t = h * 32 + i;
                const float a = sc[t];
                float2 xv = *(const float2*)&rawf[t * RPAD + 2 * pp];
                cacc.x = fmaf(a, xv.x, cacc.x);
                cacc.y = fmaf(a, xv.y, cacc.y);
            }
            ((float2*)(smem + S_CTX))[h * 64 + pp] = cacc;
        }
        __syncthreads();
        float* gout = g_tile + (size_t)tile * TSTRIDE;
        if (tid < 128) {
            const float* cp = (const float*)(smem + S_CTX);
            gout[tid] = cp[tid] + cp[128 + tid] + cp[256 + tid] + cp[384 + tid];
        }
        if (tid == 128) gout[128] = M;
        if (tid == 129) gout[129] = S;
        __syncthreads();
    }

    // ---- last CTA combines all tiles -> out ----
    __threadfence();
    if (tid == 0) {
        unsigned int old = atomicAdd(&g_done, 1u);
        ((int*)(smem + S_FLAG))[0] = (old == (unsigned int)(gridDim.x - 1));
    }
    __syncthreads();
    if (!((int*)(smem + S_FLAG))[0]) return;
    __threadfence();

    float* wgt = (float*)(smem + S_CMB);            // [64][16]
    float* invS = (float*)(smem + S_CMB + 4096);    // [64]
    if (tid < 64) {
        const float* tb = g_tile + (size_t)tid * NTILE * TSTRIDE;
        float M = -1e30f;
#pragma unroll
        for (int s = 0; s < NTILE; s++) M = fmaxf(M, tb[s * TSTRIDE + 128]);
        float S = 0.f;
#pragma unroll
        for (int s = 0; s < NTILE; s++) {
            float w = __expf(tb[s * TSTRIDE + 128] - M);
            wgt[tid * NTILE + s] = w;
            S = fmaf(tb[s * TSTRIDE + 129], w, S);
        }
        invS[tid] = 1.f / S;
    }
    __syncthreads();
#pragma unroll 4
    for (int iter = 0; iter < 32; iter++) {
        const int b = iter * 2 + (tid >> 7);
        const int d = tid & 127;
        const float* tb = g_tile + (size_t)b * NTILE * TSTRIDE;
        const float* wb = wgt + b * NTILE;
        float a = 0.f;
#pragma unroll
        for (int s = 0; s < NTILE; s++) a = fmaf(tb[s * TSTRIDE + d], wb[s], a);
        out[(size_t)b * DD + d] = a * invS[b];
    }
    if (tid == 0) g_done = 0;   // reset for next graph replay
}

// ---------------------------------------------------------------------------
extern "C" void kernel_launch(void* const* d_in, const int* in_sizes, int n_in,
                              void* d_out, int out_size) {
    const float* enc = (const float*)d_in[0];
    const float* W1w = (const float*)d_in[1];
    const float* W1b = (const float*)d_in[2];
    const float* W2w = (const float*)d_in[3];
    const float* W2b = (const float*)d_in[4];
    const float* Vw  = (const float*)d_in[5];
    // d_in[6] = V_b: softmax-invariant.
    float* out = (float*)d_out;

    cudaFuncSetAttribute(fused_kernel, cudaFuncAttributeMaxDynamicSharedMemorySize, S_TOTAL);
    fused_kernel<<<GRID, 256, S_TOTAL>>>(enc, W1w, W2w, W1b, W2b, Vw, out);
}

// round 9
// speedup vs baseline: 1.0352x; 1.0352x over previous
#include <cuda_runtime.h>
#include <cuda_bf16.h>
#include <math.h>
#include <stdint.h>

#define BB 64
#define TT 2048
#define DD 128
#define UU 128
#define WPAD 136                        // padded bf16 row -> conflict-free frags
#define NTILE 16
#define NT (BB * NTILE)                 // 1024 tiles
#define GRID 148
#define NTHR 512
#define TSTRIDE 132                     // 128 ctx + m + s + pad

__device__ float g_tile[NT * TSTRIDE];
__device__ unsigned int g_done;

// ---- smem layout (bytes) ----
#define S_BIAS 0                        // float[128]
#define S_V    512                      // float[128]
#define S_PART 1024                     // float[4][128]
#define S_SC   3072                     // float[128]
#define S_RED  3584                     // float[16]
#define S_FLAG 3648
#define S_CTX  3712                     // float[8][128]
#define S_CMB  7808                     // wgt[64][16] + invS[64]
#define S_RAW  12288                    // float[128][128]
#define S_XHI  (S_RAW + 65536)          // bf16[128][WPAD]
#define S_XLO  (S_XHI + 34816)
#define S_WHI  (S_XLO + 34816)
#define S_WLO  (S_WHI + 34816)
#define S_TOTAL (S_WLO + 34816)         // 217088 B

__device__ __forceinline__ uint32_t smem_u32(const void* p) {
    uint32_t a;
    asm("{ .reg .u64 t; cvta.to.shared.u64 t, %1; cvt.u32.u64 %0, t; }" : "=r"(a) : "l"(p));
    return a;
}
#define CP_ASYNC16(dst, src) \
    asm volatile("cp.async.cg.shared.global [%0], [%1], 16;" :: "r"(dst), "l"(src) : "memory")
#define CP_COMMIT() asm volatile("cp.async.commit_group;" ::: "memory")
#define CP_WAIT0()  asm volatile("cp.async.wait_group 0;" ::: "memory")

__device__ __forceinline__ void mma16816(float* c, const uint32_t* a, const uint32_t* b) {
    asm volatile(
        "mma.sync.aligned.m16n8k16.row.col.f32.bf16.bf16.f32 "
        "{%0,%1,%2,%3}, {%4,%5,%6,%7}, {%8,%9}, {%0,%1,%2,%3};"
        : "+f"(c[0]), "+f"(c[1]), "+f"(c[2]), "+f"(c[3])
        : "r"(a[0]), "r"(a[1]), "r"(a[2]), "r"(a[3]), "r"(b[0]), "r"(b[1]));
}
__device__ __forceinline__ float tanh_ap(float x) {
    float r;
    asm("tanh.approx.f32 %0, %1;" : "=f"(r) : "f"(x));
    return r;
}
__device__ __forceinline__ void split2(float2 v, uint32_t& hi, uint32_t& lo) {
    __nv_bfloat162 h = __float22bfloat162_rn(v);
    float2 hf = __bfloat1622float2(h);
    __nv_bfloat162 l = __float22bfloat162_rn(make_float2(v.x - hf.x, v.y - hf.y));
    hi = *(uint32_t*)&h;
    lo = *(uint32_t*)&l;
}

__global__ void __launch_bounds__(NTHR, 1) fused_kernel(const float* __restrict__ x,
                                                        const float* __restrict__ W1,
                                                        const float* __restrict__ W2,
                                                        const float* __restrict__ b1,
                                                        const float* __restrict__ b2,
                                                        const float* __restrict__ Vw,
                                                        float* __restrict__ out) {
    extern __shared__ __align__(16) char smem[];
    const int tid = threadIdx.x, wid = tid >> 5, lane = tid & 31;
    const int g = lane >> 2, q = lane & 3;
    const int wm = wid & 3, wn = wid >> 2;       // 4x4 warp grid, 32x32 tiles
    float* rawf = (float*)(smem + S_RAW);

    // ---- one-time: bias/V; Wsum staged, transpose-split into WHI/WLO ----
    if (tid < 128) {
        ((float*)(smem + S_BIAS))[tid] = b1[tid] + b2[tid];
        ((float*)(smem + S_V))[tid] = Vw[tid];
    }
    {
        const float4* w1 = (const float4*)W1;
        const float4* w2 = (const float4*)W2;
        float4* r4 = (float4*)rawf;
#pragma unroll
        for (int i = tid; i < 4096; i += NTHR) {
            float4 a = w1[i], b = w2[i];
            float4 c;
            c.x = a.x + b.x; c.y = a.y + b.y; c.z = a.z + b.z; c.w = a.w + b.w;
            r4[i] = c;
        }
    }
    __syncthreads();
    {
        const int u = tid & 127;
        const int k0 = (tid >> 7) * 32;
#pragma unroll
        for (int k = k0; k < k0 + 32; k += 2) {
            float2 w = make_float2(rawf[k * 128 + u], rawf[(k + 1) * 128 + u]);
            uint32_t hi, lo;
            split2(w, hi, lo);
            *(uint32_t*)(smem + S_WHI + (u * WPAD + k) * 2) = hi;
            *(uint32_t*)(smem + S_WLO + (u * WPAD + k) * 2) = lo;
        }
    }
    __syncthreads();

    // ---- prologue: fetch first tile ----
    const uint32_t raw_addr = smem_u32(smem + S_RAW);
    int tile = blockIdx.x;
    if (tile < NT) {
        const char* src = (const char*)(x + (size_t)tile * 16384) + tid * 16;
#pragma unroll
        for (int n = 0; n < 8; n++)
            CP_ASYNC16(raw_addr + tid * 16 + n * 8192, src + n * 8192);
        CP_COMMIT();
    }

    for (; tile < NT; tile += GRID) {
        CP_WAIT0();
        __syncthreads();

        // ---- convert raw fp32 -> bf16 hi/lo images ----
#pragma unroll
        for (int i4 = tid; i4 < 4096; i4 += NTHR) {
            int r = i4 >> 5;
            int c = (i4 & 31) << 2;
            float4 v = ((const float4*)rawf)[i4];
            uint2 hv, lv;
            split2(make_float2(v.x, v.y), hv.x, lv.x);
            split2(make_float2(v.z, v.w), hv.y, lv.y);
            size_t off = ((size_t)r * WPAD + c) * 2;
            *(uint2*)(smem + S_XHI + off) = hv;
            *(uint2*)(smem + S_XLO + off) = lv;
        }
        __syncthreads();

        // ---- prefetch next tile into raw (overlaps mainloop+epilogue) ----
        {
            const int next = tile + GRID;
            if (next < NT) {
                const char* src = (const char*)(x + (size_t)next * 16384) + tid * 16;
#pragma unroll
                for (int n = 0; n < 8; n++)
                    CP_ASYNC16(raw_addr + tid * 16 + n * 8192, src + n * 8192);
                CP_COMMIT();
            }
        }

        // ---- mainloop: 3-term bf16 split, frags from smem images ----
        float acc[2][4][4];
#pragma unroll
        for (int t = 0; t < 2; t++)
#pragma unroll
            for (int j = 0; j < 4; j++)
#pragma unroll
                for (int e = 0; e < 4; e++) acc[t][j][e] = 0.f;

#pragma unroll
        for (int ks = 0; ks < 8; ks++) {
            const int k0 = ks * 16;
            uint32_t ah[2][4], al[2][4];
#pragma unroll
            for (int t = 0; t < 2; t++) {
                const int roff = ((wm * 32 + t * 16 + g) * WPAD + k0 + 2 * q) * 2;
                const char* ph = smem + S_XHI + roff;
                const char* pl = smem + S_XLO + roff;
                ah[t][0] = *(const uint32_t*)(ph);
                ah[t][1] = *(const uint32_t*)(ph + 8 * WPAD * 2);
                ah[t][2] = *(const uint32_t*)(ph + 16);
                ah[t][3] = *(const uint32_t*)(ph + 8 * WPAD * 2 + 16);
                al[t][0] = *(const uint32_t*)(pl);
                al[t][1] = *(const uint32_t*)(pl + 8 * WPAD * 2);
                al[t][2] = *(const uint32_t*)(pl + 16);
                al[t][3] = *(const uint32_t*)(pl + 8 * WPAD * 2 + 16);
            }
#pragma unroll
            for (int j = 0; j < 4; j++) {
                const int boff = ((wn * 32 + j * 8 + g) * WPAD + k0 + 2 * q) * 2;
                uint32_t bh[2], bl[2];
                bh[0] = *(const uint32_t*)(smem + S_WHI + boff);
                bh[1] = *(const uint32_t*)(smem + S_WHI + boff + 16);
                bl[0] = *(const uint32_t*)(smem + S_WLO + boff);
                bl[1] = *(const uint32_t*)(smem + S_WLO + boff + 16);
                mma16816(acc[0][j], ah[0], bh);
                mma16816(acc[1][j], ah[1], bh);
                mma16816(acc[0][j], ah[0], bl);
                mma16816(acc[1][j], ah[1], bl);
                mma16816(acc[0][j], al[0], bh);
                mma16816(acc[1][j], al[1], bh);
            }
        }

        // ---- epilogue: tanh + V-dot ----
        const float* sBias = (const float*)(smem + S_BIAS);
        const float* sV = (const float*)(smem + S_V);
        float p[4] = {0.f, 0.f, 0.f, 0.f};
#pragma unroll
        for (int t = 0; t < 2; t++) {
#pragma unroll
            for (int j = 0; j < 4; j++) {
                const int u0 = wn * 32 + j * 8 + 2 * q;
                const float bia0 = sBias[u0], bia1 = sBias[u0 + 1];
                const float v0 = sV[u0], v1 = sV[u0 + 1];
                p[t * 2 + 0] += tanh_ap(acc[t][j][0] + bia0) * v0
                              + tanh_ap(acc[t][j][1] + bia1) * v1;
                p[t * 2 + 1] += tanh_ap(acc[t][j][2] + bia0) * v0
                              + tanh_ap(acc[t][j][3] + bia1) * v1;
            }
        }
#pragma unroll
        for (int e = 0; e < 4; e++) {
            p[e] += __shfl_xor_sync(~0u, p[e], 1);
            p[e] += __shfl_xor_sync(~0u, p[e], 2);
        }
        if (q == 0) {
            float* part = (float*)(smem + S_PART);
            part[wn * 128 + wm * 32 + g]      = p[0];
            part[wn * 128 + wm * 32 + g + 8]  = p[1];
            part[wn * 128 + wm * 32 + g + 16] = p[2];
            part[wn * 128 + wm * 32 + g + 24] = p[3];
        }
        __syncthreads();
        float* sc = (float*)(smem + S_SC);
        if (tid < 128) {
            const float* part = (const float*)(smem + S_PART);
            sc[tid] = part[tid] + part[128 + tid] + part[256 + tid] + part[384 + tid];
        }
        __syncthreads();

        // ---- tile softmax stats ----
        float* red = (float*)(smem + S_RED);
        {
            float v = sc[tid & 127];
#pragma unroll
            for (int off = 16; off > 0; off >>= 1) v = fmaxf(v, __shfl_xor_sync(~0u, v, off));
            if (lane == 0) red[wid] = v;
        }
        __syncthreads();
        float M = red[0];
#pragma unroll
        for (int i = 1; i < 16; i++) M = fmaxf(M, red[i]);
        __syncthreads();
        float e_val = 0.f;
        if (tid < 128) e_val = __expf(sc[tid] - M);
        {
            float v = e_val;
#pragma unroll
            for (int off = 16; off > 0; off >>= 1) v += __shfl_xor_sync(~0u, v, off);
            if (lane == 0) red[wid] = v;
        }
        if (tid < 128) sc[tid] = e_val;
        __syncthreads();
        float S = red[0];
#pragma unroll
        for (int i = 1; i < 4; i++) S += red[i];

        // ---- tile context from hi+lo images (raw holds next tile) ----
        {
            const int h = tid >> 6;          // 8 groups of 16 tokens
            const int pp = tid & 63;         // d-pair
            float2 cacc = make_float2(0.f, 0.f);
#pragma unroll 8
            for (int i = 0; i < 16; i++) {
                const int t = h * 16 + i;
                const float a = sc[t];
                const int off = (t * WPAD + 2 * pp) * 2;
                __nv_bfloat162 xh = *(const __nv_bfloat162*)(smem + S_XHI + off);
                __nv_bfloat162 xl = *(const __nv_bfloat162*)(smem + S_XLO + off);
                float2 fh = __bfloat1622float2(xh);
                float2 fl = __bfloat1622float2(xl);
                cacc.x = fmaf(a, fh.x + fl.x, cacc.x);
                cacc.y = fmaf(a, fh.y + fl.y, cacc.y);
            }
            ((float2*)(smem + S_CTX))[h * 64 + pp] = cacc;
        }
        __syncthreads();
        float* gout = g_tile + (size_t)tile * TSTRIDE;
        if (tid < 128) {
            const float* cp = (const float*)(smem + S_CTX);
            float a = cp[tid];
#pragma unroll
            for (int hh = 1; hh < 8; hh++) a += cp[hh * 128 + tid];
            gout[tid] = a;
        }
        if (tid == 128) gout[128] = M;
        if (tid == 129) gout[129] = S;
        __syncthreads();
    }

    // ---- last CTA combines all tiles -> out ----
    __threadfence();
    if (tid == 0) {
        unsigned int old = atomicAdd(&g_done, 1u);
        ((int*)(smem + S_FLAG))[0] = (old == (unsigned int)(gridDim.x - 1));
    }
    __syncthreads();
    if (!((int*)(smem + S_FLAG))[0]) return;
    __threadfence();

    float* wgt = (float*)(smem + S_CMB);            // [64][16]
    float* invS = (float*)(smem + S_CMB + 4096);    // [64]
    if (tid < 64) {
        const float* tb = g_tile + (size_t)tid * NTILE * TSTRIDE;
        float M = -1e30f;
#pragma unroll
        for (int s = 0; s < NTILE; s++) M = fmaxf(M, tb[s * TSTRIDE + 128]);
        float S = 0.f;
#pragma unroll
        for (int s = 0; s < NTILE; s++) {
            float w = __expf(tb[s * TSTRIDE + 128] - M);
            wgt[tid * NTILE + s] = w;
            S = fmaf(tb[s * TSTRIDE + 129], w, S);
        }
        invS[tid] = 1.f / S;
    }
    __syncthreads();
#pragma unroll 2
    for (int iter = 0; iter < 16; iter++) {
        const int b = iter * 4 + (tid >> 7);
        const int d = tid & 127;
        const float* tb = g_tile + (size_t)b * NTILE * TSTRIDE;
        const float* wb = wgt + b * NTILE;
        float a = 0.f;
#pragma unroll
        for (int s = 0; s < NTILE; s++) a = fmaf(tb[s * TSTRIDE + d], wb[s], a);
        out[(size_t)b * DD + d] = a * invS[b];
    }
    if (tid == 0) g_done = 0;   // reset for next graph replay
}

// ---------------------------------------------------------------------------
extern "C" void kernel_launch(void* const* d_in, const int* in_sizes, int n_in,
                              void* d_out, int out_size) {
    const float* enc = (const float*)d_in[0];
    const float* W1w = (const float*)d_in[1];
    const float* W1b = (const float*)d_in[2];
    const float* W2w = (const float*)d_in[3];
    const float* W2b = (const float*)d_in[4];
    const float* Vw  = (const float*)d_in[5];
    // d_in[6] = V_b: softmax-invariant.
    float* out = (float*)d_out;

    cudaFuncSetAttribute(fused_kernel, cudaFuncAttributeMaxDynamicSharedMemorySize, S_TOTAL);
    fused_kernel<<<GRID, NTHR, S_TOTAL>>>(enc, W1w, W2w, W1b, W2b, Vw, out);
}